// round 16
// baseline (speedup 1.0000x reference)
#include <cuda_runtime.h>
#include <cuda_bf16.h>

// Problem constants:
//   bs=4, c=3, dsrc=1, h=w=128, d=8, K=10 -> K1=11, out_channels=66
//   out shape (bs, 66, d, h, w) float32
#define BS   4
#define CCH  3
#define HH   128
#define WW   128
#define DD   8
#define KK   10
#define K1   (KK + 1)
#define HW   (HH * WW)          // 16384
#define NREST (BS * DD * K1)    // 352

// uniform-r 5-element window select out of two float4s (r uniform per block)
__device__ __forceinline__ void sel5(const float4& qa, const float4& qb, int r,
                                     float* o) {
    switch (r) {
        case 0:  o[0]=qa.x; o[1]=qa.y; o[2]=qa.z; o[3]=qa.w; o[4]=qb.x; break;
        case 1:  o[0]=qa.y; o[1]=qa.z; o[2]=qa.w; o[3]=qb.x; o[4]=qb.y; break;
        case 2:  o[0]=qa.z; o[1]=qa.w; o[2]=qb.x; o[3]=qb.y; o[4]=qb.z; break;
        default: o[0]=qa.w; o[1]=qb.x; o[2]=qb.y; o[3]=qb.z; o[4]=qb.w; break;
    }
}

// ---------------------------------------------------------------------------
// Single fused kernel (R12 shuffle-gather body, natural occupancy) with
// STREAMING OUTPUT STORES (__stcs, evict-first): the 138 MB output stream no
// longer displaces the L2-resident source image, so gathers stay L2/L1 hits
// and DRAM read re-fetches disappear.
// Thread map: lane = x-quad (x = 4*lane..4*lane+3), warp = one y-row,
//   block = 8 y-rows of one block-uniform (b,dd,k1).
// Prologue: per-block separable gaussian tables in smem, one __expf/thread.
// Gather per channel: one aligned quad per source row, rows combined with
//   y-weights, masked by true column labels B..B+3; neighbor quad (labels
//   B+4..B+7) via __shfl_down (o0(lane+1)==o1(lane), clamping included);
//   lane 31 loads its neighbor quad itself.
// ---------------------------------------------------------------------------
__global__ __launch_bounds__(256)
void movement_embed_kernel(const float* __restrict__ src,
                           const float* __restrict__ kp_drv,
                           const float* __restrict__ kp_src,
                           float* __restrict__ out) {
    const int t    = threadIdx.x;              // 0..255
    const int tid  = blockIdx.x * 256 + t;
    const int lane = t & 31;                   // x quad: x = lane*4..lane*4+3
    const int y    = (tid >> 5) & (HH - 1);    // uniform per warp
    const int rest = tid >> 12;                // uniform per block, 0..351
    const int k1 = rest % K1;
    const int bd = rest / K1;                  // b*8 + dd
    const int b  = bd >> 3;
    const int xb = lane << 2;

    float mx = 0.0f, my = 0.0f, diffx = 0.0f, diffy = 0.0f;
    if (k1 > 0) {
        const int kidx = bd * KK + (k1 - 1);
        mx = kp_drv[2 * kidx + 0];
        my = kp_drv[2 * kidx + 1];
        diffx = kp_src[2 * kidx + 0] - mx;
        diffy = kp_src[2 * kidx + 1] - my;
    }

    // ---- prologue: per-block separable tables, one __expf per thread ----
    __shared__ float tab[256];                 // [0..127]=ex, [128..255]=ey
    __shared__ float red[8];
    {
        const float g = (float)(t & 127) * (2.0f / (WW - 1)) - 1.0f;
        const float m = (t < 128) ? mx : my;
        const float dg = g - m;
        const float e = __expf(-50.0f * dg * dg);   // -0.5/0.01
        tab[t] = e;
        float s = e;
        #pragma unroll
        for (int off = 16; off > 0; off >>= 1)
            s += __shfl_xor_sync(0xFFFFFFFFu, s, off);
        if (lane == 0) red[t >> 5] = s;
    }
    __syncthreads();

    float4 heat4 = make_float4(0.f, 0.f, 0.f, 0.f);
    if (k1 > 0) {
        const float Sx = red[0] + red[1] + red[2] + red[3];
        const float Sy = red[4] + red[5] + red[6] + red[7];
        const float eyv = tab[128 + y] / (Sx * Sy);
        const float4 ex4 = *(const float4*)&tab[xb];
        heat4 = make_float4(ex4.x * eyv, ex4.y * eyv, ex4.z * eyv, ex4.w * eyv);
    }

    // ---- bilinear sample at constant per-block pixel shift, zero padding ----
    const float sx = diffx * (0.5f * (WW - 1));   // * 63.5
    const float sy = diffy * (0.5f * (HH - 1));

    const float py  = (float)y + sy;
    const float fy  = floorf(py);
    const int   iy0 = (int)fy, iy1 = iy0 + 1;
    const float wy1 = py - fy, wy0 = 1.0f - wy1;
    const float wy0v = wy0 * (((unsigned)iy0 < (unsigned)HH) ? 1.0f : 0.0f);
    const float wy1v = wy1 * (((unsigned)iy1 < (unsigned)HH) ? 1.0f : 0.0f);
    const int cy0 = min(max(iy0, 0), HH - 1);
    const int cy1 = min(max(iy1, 0), HH - 1);

    const float fsx = floorf(sx);
    const int   isx = (int)fsx;
    const float wx1 = sx - fsx, wx0 = 1.0f - wx1;
    const int   r   = isx & 3;                    // uniform per block
    const int   B   = xb + (isx & ~3);            // aligned window base (own quad)
    const int   o0  = min(max(B,     0), WW - 4); // own quad address
    const int   o1  = min(max(B + 4, 0), WW - 4); // lane-31 extra quad address

    // mask for own quad labels B..B+3, and (lane 31 only) labels B+4..B+7
    float m0[4], m1[4];
    #pragma unroll
    for (int e = 0; e < 4; e++) {
        m0[e] = ((unsigned)(B + e)     < (unsigned)WW) ? 1.0f : 0.0f;
        m1[e] = ((unsigned)(B + 4 + e) < (unsigned)WW) ? 1.0f : 0.0f;
    }

    // ---- output (streaming stores: evict-first, don't pollute L2) ----
    const int chs  = DD * HW;
    const int base = ((b * (K1 * 6) + k1 * 6) * DD + (bd & (DD - 1))) * HW
                     + (y << 7) + xb;
    float* o = out + base;

    __stcs((float4*)(o),           heat4);
    __stcs((float4*)(o + chs),     make_float4(diffx, diffx, diffx, diffx));
    __stcs((float4*)(o + 2 * chs), make_float4(diffy, diffy, diffy, diffy));

    const float* im = src + b * (CCH * HW);
    #pragma unroll
    for (int cc = 0; cc < CCH; cc++) {
        const float* r0p = im + cc * HW + (cy0 << 7);
        const float* r1p = im + cc * HW + (cy1 << 7);
        const float4 q0 = *(const float4*)(r0p + o0);
        const float4 q1 = *(const float4*)(r1p + o0);

        // combine rows + mask own quad (labels B..B+3)
        float4 cq;
        cq.x = (wy0v * q0.x + wy1v * q1.x) * m0[0];
        cq.y = (wy0v * q0.y + wy1v * q1.y) * m0[1];
        cq.z = (wy0v * q0.z + wy1v * q1.z) * m0[2];
        cq.w = (wy0v * q0.w + wy1v * q1.w) * m0[3];

        // neighbor quad (labels B+4..B+7), already combined+masked by neighbor
        float4 cn;
        cn.x = __shfl_down_sync(0xFFFFFFFFu, cq.x, 1);
        cn.y = __shfl_down_sync(0xFFFFFFFFu, cq.y, 1);
        cn.z = __shfl_down_sync(0xFFFFFFFFu, cq.z, 1);
        cn.w = __shfl_down_sync(0xFFFFFFFFu, cq.w, 1);
        if (lane == 31) {
            const float4 p0 = *(const float4*)(r0p + o1);
            const float4 p1 = *(const float4*)(r1p + o1);
            cn.x = (wy0v * p0.x + wy1v * p1.x) * m1[0];
            cn.y = (wy0v * p0.y + wy1v * p1.y) * m1[1];
            cn.z = (wy0v * p0.z + wy1v * p1.z) * m1[2];
            cn.w = (wy0v * p0.w + wy1v * p1.w) * m1[3];
        }

        float c[5];
        sel5(cq, cn, r, c);                 // columns ix0..ix0+4 (B+r = xb+isx)
        float v[4];
        #pragma unroll
        for (int i = 0; i < 4; i++)
            v[i] = wx0 * c[i] + wx1 * c[i + 1];
        __stcs((float4*)(o + (3 + cc) * chs),
               make_float4(v[0], v[1], v[2], v[3]));
    }
}

// ---------------------------------------------------------------------------
extern "C" void kernel_launch(void* const* d_in, const int* in_sizes, int n_in,
                              void* d_out, int out_size) {
    const float* src    = (const float*)d_in[0];  // (4,3,1,128,128)
    const float* kp_drv = (const float*)d_in[1];  // (4,8,10,2)
    const float* kp_src = (const float*)d_in[2];  // (4,8,10,2)
    float* out = (float*)d_out;                   // (4,66,8,128,128)

    const int total   = NREST * HH * (WW / 4);    // 1,441,792 threads (exact)
    const int threads = 256;
    const int blocks  = total / threads;          // 5632
    movement_embed_kernel<<<blocks, threads>>>(src, kp_drv, kp_src, out);
}

// round 17
// speedup vs baseline: 1.3824x; 1.3824x over previous
#include <cuda_runtime.h>
#include <cuda_bf16.h>

// Problem constants:
//   bs=4, c=3, dsrc=1, h=w=128, d=8, K=10 -> K1=11, out_channels=66
//   out shape (bs, 66, d, h, w) float32
#define BS   4
#define CCH  3
#define HH   128
#define WW   128
#define DD   8
#define KK   10
#define K1   (KK + 1)
#define HW   (HH * WW)          // 16384
#define NREST (BS * DD * K1)    // 352

// uniform-r 5-element window select out of two float4s (r uniform per block)
__device__ __forceinline__ void sel5(const float4& qa, const float4& qb, int r,
                                     float* o) {
    switch (r) {
        case 0:  o[0]=qa.x; o[1]=qa.y; o[2]=qa.z; o[3]=qa.w; o[4]=qb.x; break;
        case 1:  o[0]=qa.y; o[1]=qa.z; o[2]=qa.w; o[3]=qb.x; o[4]=qb.y; break;
        case 2:  o[0]=qa.z; o[1]=qa.w; o[2]=qb.x; o[3]=qb.y; o[4]=qb.z; break;
        default: o[0]=qa.w; o[1]=qb.x; o[2]=qb.y; o[3]=qb.z; o[4]=qb.w; break;
    }
}

// ---------------------------------------------------------------------------
// Single fused kernel = R7 body + light smem table prologue (R11, best).
// Thread map: lane = x-quad (x = 4*lane..4*lane+3), warp = one y-row,
//   block = 8 y-rows of one block-uniform (b,dd,k1).
// Prologue: 256 threads build ex[128], ey[128] in smem with ONE __expf each,
//   warp-reduce partial sums -> red[8], one __syncthreads; Sx,Sy from red.
//   (2-D gaussian sum factorizes: sum2d = Sx*Sy.)
// Body: 6 float4 stores per thread (heat, diffx, diffy, 3 bilinear channels).
// Gather: block-uniform misalignment r = floor(sx)&3 -> two aligned float4
//   loads cover each 5-column window; clamped loads only carry fully
//   out-of-range column labels, so the zero-mask by true column is exact.
// This configuration sits at the LTS store-bandwidth wall (~5.4 TB/s for the
// 138.4 MB output stream); load-side and occupancy perturbations measured
// neutral-to-negative (R12/R15/R16).
// ---------------------------------------------------------------------------
__global__ __launch_bounds__(256)
void movement_embed_kernel(const float* __restrict__ src,
                           const float* __restrict__ kp_drv,
                           const float* __restrict__ kp_src,
                           float* __restrict__ out) {
    const int t    = threadIdx.x;              // 0..255
    const int tid  = blockIdx.x * 256 + t;
    const int lane = t & 31;                   // x quad: x = lane*4..lane*4+3
    const int y    = (tid >> 5) & (HH - 1);    // uniform per warp
    const int rest = tid >> 12;                // uniform per block, 0..351
    const int k1 = rest % K1;
    const int bd = rest / K1;                  // b*8 + dd
    const int b  = bd >> 3;
    const int xb = lane << 2;

    float mx = 0.0f, my = 0.0f, diffx = 0.0f, diffy = 0.0f;
    if (k1 > 0) {
        const int kidx = bd * KK + (k1 - 1);
        mx = kp_drv[2 * kidx + 0];
        my = kp_drv[2 * kidx + 1];
        diffx = kp_src[2 * kidx + 0] - mx;
        diffy = kp_src[2 * kidx + 1] - my;
    }

    // ---- prologue: per-block separable tables, one __expf per thread ----
    __shared__ float tab[256];                 // [0..127]=ex, [128..255]=ey
    __shared__ float red[8];
    {
        const float g = (float)(t & 127) * (2.0f / (WW - 1)) - 1.0f;
        const float m = (t < 128) ? mx : my;
        const float dg = g - m;
        const float e = __expf(-50.0f * dg * dg);   // -0.5/0.01
        tab[t] = e;
        float s = e;
        #pragma unroll
        for (int off = 16; off > 0; off >>= 1)
            s += __shfl_xor_sync(0xFFFFFFFFu, s, off);
        if (lane == 0) red[t >> 5] = s;
    }
    __syncthreads();

    float4 heat4 = make_float4(0.f, 0.f, 0.f, 0.f);
    if (k1 > 0) {
        const float Sx = red[0] + red[1] + red[2] + red[3];
        const float Sy = red[4] + red[5] + red[6] + red[7];
        const float eyv = tab[128 + y] / (Sx * Sy);
        const float4 ex4 = *(const float4*)&tab[xb];
        heat4 = make_float4(ex4.x * eyv, ex4.y * eyv, ex4.z * eyv, ex4.w * eyv);
    }

    // ---- bilinear sample at constant per-block pixel shift, zero padding ----
    const float sx = diffx * (0.5f * (WW - 1));   // * 63.5
    const float sy = diffy * (0.5f * (HH - 1));

    const float py  = (float)y + sy;
    const float fy  = floorf(py);
    const int   iy0 = (int)fy, iy1 = iy0 + 1;
    const float wy1 = py - fy, wy0 = 1.0f - wy1;
    const float wy0v = wy0 * (((unsigned)iy0 < (unsigned)HH) ? 1.0f : 0.0f);
    const float wy1v = wy1 * (((unsigned)iy1 < (unsigned)HH) ? 1.0f : 0.0f);
    const int cy0 = min(max(iy0, 0), HH - 1);
    const int cy1 = min(max(iy1, 0), HH - 1);

    const float fsx = floorf(sx);
    const int   isx = (int)fsx;
    const float wx1 = sx - fsx, wx0 = 1.0f - wx1;
    const int   r   = isx & 3;                    // uniform per block
    const int   ix0 = xb + isx;                   // first needed column
    const int   B   = xb + (isx & ~3);            // aligned window base
    const int   o0  = min(max(B,     0), WW - 4);
    const int   o1  = min(max(B + 4, 0), WW - 4);

    float amask[5];
    #pragma unroll
    for (int j = 0; j < 5; j++)
        amask[j] = ((unsigned)(ix0 + j) < (unsigned)WW) ? 1.0f : 0.0f;

    // ---- output ----
    const int chs  = DD * HW;
    const int base = ((b * (K1 * 6) + k1 * 6) * DD + (bd & (DD - 1))) * HW
                     + (y << 7) + xb;
    float* o = out + base;

    *(float4*)(o)           = heat4;
    *(float4*)(o + chs)     = make_float4(diffx, diffx, diffx, diffx);
    *(float4*)(o + 2 * chs) = make_float4(diffy, diffy, diffy, diffy);

    const float* im = src + b * (CCH * HW);
    #pragma unroll
    for (int cc = 0; cc < CCH; cc++) {
        const float* r0p = im + cc * HW + (cy0 << 7);
        const float* r1p = im + cc * HW + (cy1 << 7);
        const float4 q00 = *(const float4*)(r0p + o0);
        const float4 q01 = *(const float4*)(r0p + o1);
        const float4 q10 = *(const float4*)(r1p + o0);
        const float4 q11 = *(const float4*)(r1p + o1);

        float a0[5], a1[5];
        sel5(q00, q01, r, a0);
        sel5(q10, q11, r, a1);
        #pragma unroll
        for (int j = 0; j < 5; j++) { a0[j] *= amask[j]; a1[j] *= amask[j]; }

        float v[4];
        #pragma unroll
        for (int i = 0; i < 4; i++)
            v[i] = wy0v * (wx0 * a0[i] + wx1 * a0[i + 1])
                 + wy1v * (wx0 * a1[i] + wx1 * a1[i + 1]);
        *(float4*)(o + (3 + cc) * chs) = make_float4(v[0], v[1], v[2], v[3]);
    }
}

// ---------------------------------------------------------------------------
extern "C" void kernel_launch(void* const* d_in, const int* in_sizes, int n_in,
                              void* d_out, int out_size) {
    const float* src    = (const float*)d_in[0];  // (4,3,1,128,128)
    const float* kp_drv = (const float*)d_in[1];  // (4,8,10,2)
    const float* kp_src = (const float*)d_in[2];  // (4,8,10,2)
    float* out = (float*)d_out;                   // (4,66,8,128,128)

    const int total   = NREST * HH * (WW / 4);    // 1,441,792 threads (exact)
    const int threads = 256;
    const int blocks  = total / threads;          // 5632
    movement_embed_kernel<<<blocks, threads>>>(src, kp_drv, kp_src, out);
}